// round 3
// baseline (speedup 1.0000x reference)
#include <cuda_runtime.h>

// Problem dims (fixed by reference setup_inputs)
constexpr int B_ = 8;
constexpr int T_ = 100;
constexpr int S_ = 400;
constexpr int H_ = 256;

constexpr int TT  = 2;    // t-rows per CTA in attn pass
constexpr int SCH = 64;   // s-rows per SMEM tile
constexpr int PAD = 260;  // padded row stride (floats); 260%32==4 -> conflict-free LDS.128

// SMEM partition offsets (floats)
constexpr int OFF_WH  = 0;                      // [SCH][PAD]
constexpr int OFF_WS  = SCH * PAD;              // TT*256
constexpr int OFF_V   = OFF_WS + TT * H_;       // 256
constexpr int OFF_WC  = OFF_V + H_;             // 256
constexpr int OFF_E   = OFF_WC + H_;            // TT*400
constexpr int OFF_COV = OFF_E + TT * S_;        // TT*400
constexpr int OFF_RED = OFF_COV + TT * S_;      // 12
constexpr int SMEM_FLOATS = OFF_RED + 16;
constexpr size_t SMEM_BYTES = SMEM_FLOATS * sizeof(float);

// Scratch (device globals — no allocation allowed)
__device__ float g_Wh[B_ * S_ * H_];    // enc @ W_h + b_attn
__device__ float g_Ws[B_ * T_ * H_];    // dec @ W_s
__device__ float g_Apre[B_ * T_ * S_];  // A_prelim
__device__ float g_cov[B_ * T_ * S_];   // shifted cumsum of A_prelim

__device__ __forceinline__ float fast_tanh(float x) {
    float y;
    asm("tanh.approx.f32 %0, %1;" : "=f"(y) : "f"(x));
    return y;
}

// ---------------------------------------------------------------------------
// 64x64-tile SGEMM, 256 threads, 4x4 per thread, K-chunk 16.
// ---------------------------------------------------------------------------
__global__ __launch_bounds__(256) void sgemm64(
    const float* __restrict__ A, const float* __restrict__ Bm,
    float* __restrict__ C, int M, int N, int K,
    const float* __restrict__ bias)
{
    int m0 = blockIdx.y * 64, n0 = blockIdx.x * 64;
    int tid = threadIdx.x;
    int tx = tid & 15, ty = tid >> 4;

    __shared__ float As[16][68];
    __shared__ float Bs[16][68];

    float acc[4][4] = {};

    int lm  = tid >> 2;
    int lk4 = tid & 3;
    int bkr = tid >> 4;
    int bnc = tid & 15;

    for (int k = 0; k < K; k += 16) {
        float4 av = make_float4(0.f, 0.f, 0.f, 0.f);
        int gm = m0 + lm;
        if (gm < M) av = *(const float4*)(A + (size_t)gm * K + k + lk4 * 4);
        As[lk4 * 4 + 0][lm] = av.x;
        As[lk4 * 4 + 1][lm] = av.y;
        As[lk4 * 4 + 2][lm] = av.z;
        As[lk4 * 4 + 3][lm] = av.w;
        float4 bv = *(const float4*)(Bm + (size_t)(k + bkr) * N + n0 + bnc * 4);
        *(float4*)&Bs[bkr][bnc * 4] = bv;
        __syncthreads();
#pragma unroll
        for (int kk = 0; kk < 16; kk++) {
            float4 a = *(float4*)&As[kk][ty * 4];
            float4 b = *(float4*)&Bs[kk][tx * 4];
            acc[0][0] = fmaf(a.x, b.x, acc[0][0]);
            acc[0][1] = fmaf(a.x, b.y, acc[0][1]);
            acc[0][2] = fmaf(a.x, b.z, acc[0][2]);
            acc[0][3] = fmaf(a.x, b.w, acc[0][3]);
            acc[1][0] = fmaf(a.y, b.x, acc[1][0]);
            acc[1][1] = fmaf(a.y, b.y, acc[1][1]);
            acc[1][2] = fmaf(a.y, b.z, acc[1][2]);
            acc[1][3] = fmaf(a.y, b.w, acc[1][3]);
            acc[2][0] = fmaf(a.z, b.x, acc[2][0]);
            acc[2][1] = fmaf(a.z, b.y, acc[2][1]);
            acc[2][2] = fmaf(a.z, b.z, acc[2][2]);
            acc[2][3] = fmaf(a.z, b.w, acc[2][3]);
            acc[3][0] = fmaf(a.w, b.x, acc[3][0]);
            acc[3][1] = fmaf(a.w, b.y, acc[3][1]);
            acc[3][2] = fmaf(a.w, b.z, acc[3][2]);
            acc[3][3] = fmaf(a.w, b.w, acc[3][3]);
        }
        __syncthreads();
    }

#pragma unroll
    for (int i = 0; i < 4; i++) {
        int gm = m0 + ty * 4 + i;
        if (gm < M) {
#pragma unroll
            for (int j = 0; j < 4; j++) {
                int gn = n0 + tx * 4 + j;
                float bi = bias ? bias[gn] : 0.f;
                C[(size_t)gm * N + gn] = acc[i][j] + bi;
            }
        }
    }
}

// ---------------------------------------------------------------------------
// Batched SGEMM, 32x32 tile, 2x2 per thread (Ws + context).
// ---------------------------------------------------------------------------
__global__ __launch_bounds__(256) void sgemm32(
    const float* __restrict__ A, const float* __restrict__ Bm,
    float* __restrict__ C, int M, int N, int K,
    const float* __restrict__ bias,
    long long sA, long long sB, long long sC)
{
    int bz = blockIdx.z;
    A  += (size_t)bz * sA;
    Bm += (size_t)bz * sB;
    C  += (size_t)bz * sC;

    int m0 = blockIdx.y * 32, n0 = blockIdx.x * 32;
    int tid = threadIdx.x;
    int tx = tid & 15, ty = tid >> 4;

    __shared__ float As[32][17];
    __shared__ float Bs[16][33];

    float c00 = 0.f, c01 = 0.f, c10 = 0.f, c11 = 0.f;

    for (int k = 0; k < K; k += 16) {
#pragma unroll
        for (int i = 0; i < 2; i++) {
            int e = tid + i * 256;
            int m = e >> 4, kk = e & 15;
            int gm = m0 + m;
            As[m][kk] = (gm < M) ? A[(size_t)gm * K + k + kk] : 0.f;
            int kk2 = e >> 5, n = e & 31;
            Bs[kk2][n] = Bm[(size_t)(k + kk2) * N + n0 + n];
        }
        __syncthreads();
#pragma unroll
        for (int kk = 0; kk < 16; kk++) {
            float a0 = As[ty][kk], a1 = As[ty + 16][kk];
            float b0 = Bs[kk][tx], b1 = Bs[kk][tx + 16];
            c00 = fmaf(a0, b0, c00);
            c01 = fmaf(a0, b1, c01);
            c10 = fmaf(a1, b0, c10);
            c11 = fmaf(a1, b1, c11);
        }
        __syncthreads();
    }

    float bi0 = bias ? bias[n0 + tx]      : 0.f;
    float bi1 = bias ? bias[n0 + tx + 16] : 0.f;
    if (m0 + ty < M) {
        C[(size_t)(m0 + ty) * N + n0 + tx]      = c00 + bi0;
        C[(size_t)(m0 + ty) * N + n0 + tx + 16] = c01 + bi1;
    }
    if (m0 + ty + 16 < M) {
        C[(size_t)(m0 + ty + 16) * N + n0 + tx]      = c10 + bi0;
        C[(size_t)(m0 + ty + 16) * N + n0 + tx + 16] = c11 + bi1;
    }
}

// ---------------------------------------------------------------------------
// attn_pass v2: thread-per-(t,s), no warp reductions.
// CTA = (b, TT t-rows), 128 threads = TT x 64 s-lanes. S tiled by SCH.
// ---------------------------------------------------------------------------
template <bool PASS2>
__global__ __launch_bounds__(128) void attn_pass(
    const unsigned char* __restrict__ mask,
    const float* __restrict__ v,
    const float* __restrict__ wc,
    float* __restrict__ AoutParam,
    float* __restrict__ loss)
{
    extern __shared__ float sm[];
    float*  sWh  = sm + OFF_WH;                 // [SCH][PAD]
    float4* sWs  = (float4*)(sm + OFF_WS);      // [TT][64]
    float4* sV   = (float4*)(sm + OFF_V);       // [64]
    float4* sWc  = (float4*)(sm + OFF_WC);      // [64]
    float*  sE   = sm + OFF_E;                  // [TT][400]
    float*  sCov = sm + OFF_COV;                // [TT][400]
    float*  sRed = sm + OFF_RED;                // scratch reductions

    int tid  = threadIdx.x;
    int b    = blockIdx.x / (T_ / TT);
    int t0   = (blockIdx.x % (T_ / TT)) * TT;

    // Preload v, wc, Ws rows, cov rows.
    if (tid < 64) sV[tid] = ((const float4*)v)[tid];
    else if (PASS2) sWc[tid - 64] = ((const float4*)wc)[tid - 64];
    {
        int row = tid >> 6, h4 = tid & 63;  // TT*64 == 128 exactly
        sWs[row * 64 + h4] =
            ((const float4*)(g_Ws + ((size_t)b * T_ + t0 + row) * H_))[h4];
    }
    if (PASS2) {
        for (int i = tid; i < TT * S_; i += 128) {
            int tl = i / S_, s = i % S_;
            sCov[tl * S_ + s] = g_cov[((size_t)b * T_ + t0 + tl) * S_ + s];
        }
    }

    const float* whBase = g_Wh + (size_t)b * S_ * H_;
    int ti = tid >> 6, si = tid & 63;

    for (int s0 = 0; s0 < S_; s0 += SCH) {
        int rows = min(SCH, S_ - s0);
        __syncthreads();
        // Load Wh tile [rows][256] into padded SMEM
        for (int i = tid; i < rows * 64; i += 128) {
            int row = i >> 6, h4 = i & 63;
            float4 w = *(const float4*)(whBase + (size_t)(s0 + row) * H_ + h4 * 4);
            *(float4*)&sWh[row * PAD + h4 * 4] = w;
        }
        __syncthreads();

        if (si < rows) {
            int s = s0 + si;
            float c = PASS2 ? sCov[ti * S_ + s] : 0.f;
            const float* whRow = sWh + si * PAD;
            const float4* wsRow = sWs + ti * 64;
            float ax = 0.f, ay = 0.f, az = 0.f, aw = 0.f;
#pragma unroll 8
            for (int h4 = 0; h4 < 64; h4++) {
                float4 wh = *(const float4*)(whRow + h4 * 4);
                float4 ws = wsRow[h4];
                float4 vv = sV[h4];
                if (PASS2) {
                    float4 wcv = sWc[h4];
                    ax = fmaf(vv.x, fast_tanh(fmaf(c, wcv.x, wh.x + ws.x)), ax);
                    ay = fmaf(vv.y, fast_tanh(fmaf(c, wcv.y, wh.y + ws.y)), ay);
                    az = fmaf(vv.z, fast_tanh(fmaf(c, wcv.z, wh.z + ws.z)), az);
                    aw = fmaf(vv.w, fast_tanh(fmaf(c, wcv.w, wh.w + ws.w)), aw);
                } else {
                    ax = fmaf(vv.x, fast_tanh(wh.x + ws.x), ax);
                    ay = fmaf(vv.y, fast_tanh(wh.y + ws.y), ay);
                    az = fmaf(vv.z, fast_tanh(wh.z + ws.z), az);
                    aw = fmaf(vv.w, fast_tanh(wh.w + ws.w), aw);
                }
            }
            float e = (ax + ay) + (az + aw);
            e = fminf(fmaxf(e, -30.0f), 30.0f);
            if (mask[b * S_ + s]) e = -1e30f;
            sE[ti * S_ + s] = e;
        }
    }
    __syncthreads();

    // Softmax per t-row: 64 threads (2 warps) per row.
    int tl = tid >> 6;
    int r  = tid & 63;
    int w2 = (tid >> 5) & 1;  // warp within row
    int lane = tid & 31;

    float m = -1e30f;
    for (int s = r; s < S_; s += 64) m = fmaxf(m, sE[tl * S_ + s]);
#pragma unroll
    for (int o = 16; o; o >>= 1) m = fmaxf(m, __shfl_xor_sync(0xffffffffu, m, o));
    if (lane == 0) sRed[tl * 2 + w2] = m;
    __syncthreads();
    m = fmaxf(sRed[tl * 2], sRed[tl * 2 + 1]);

    float sum = 0.f;
    for (int s = r; s < S_; s += 64) {
        float ex = __expf(sE[tl * S_ + s] - m);
        sE[tl * S_ + s] = ex;
        sum += ex;
    }
#pragma unroll
    for (int o = 16; o; o >>= 1) sum += __shfl_xor_sync(0xffffffffu, sum, o);
    if (lane == 0) sRed[4 + tl * 2 + w2] = sum;
    __syncthreads();
    sum = sRed[4 + tl * 2] + sRed[4 + tl * 2 + 1];
    float inv = 1.0f / fmaxf(sum, 1e-30f);

    size_t rowOff = ((size_t)b * T_ + t0 + tl) * S_;
    float* Aout = (PASS2 ? AoutParam : g_Apre) + rowOff;
    float lacc = 0.f;
    for (int s = r; s < S_; s += 64) {
        float a = sE[tl * S_ + s] * inv;
        Aout[s] = a;
        if (PASS2) lacc += fminf(a, sCov[tl * S_ + s]);
    }
    if (PASS2) {
#pragma unroll
        for (int o = 16; o; o >>= 1) lacc += __shfl_xor_sync(0xffffffffu, lacc, o);
        if (lane == 0) sRed[8 + tl * 2 + w2] = lacc;
        __syncthreads();
        if (r == 0) {
            float p = sRed[8 + tl * 2] + sRed[8 + tl * 2 + 1];
            atomicAdd(loss, p * (1.0f / (B_ * T_)));
        }
    }
}

// ---------------------------------------------------------------------------
// cumsum v3: one warp per (b,s); 4 up-front loads + 4 warp scans.
// ---------------------------------------------------------------------------
__global__ __launch_bounds__(256) void cumsum_k(float* __restrict__ loss)
{
    int gt = blockIdx.x * blockDim.x + threadIdx.x;
    int gw = gt >> 5;
    int lane = gt & 31;
    if (gt == 0) *loss = 0.f;
    if (gw >= B_ * S_) return;
    int b = gw / S_, s = gw % S_;
    const float* src = g_Apre + (size_t)b * T_ * S_ + s;
    float*       dst = g_cov  + (size_t)b * T_ * S_ + s;

    float vals[4];
#pragma unroll
    for (int k = 0; k < 4; k++) {
        int t = k * 32 + lane;
        vals[k] = (t < T_) ? src[(size_t)t * S_] : 0.f;
    }
    float run = 0.f;
#pragma unroll
    for (int k = 0; k < 4; k++) {
        float x = vals[k];
#pragma unroll
        for (int off = 1; off < 32; off <<= 1) {
            float y = __shfl_up_sync(0xffffffffu, x, off);
            if (lane >= off) x += y;
        }
        int t = k * 32 + lane;
        if (t < T_) dst[(size_t)t * S_] = run + (x - vals[k]);
        run += __shfl_sync(0xffffffffu, x, 31);
    }
}

// ---------------------------------------------------------------------------
extern "C" void kernel_launch(void* const* d_in, const int* in_sizes, int n_in,
                              void* d_out, int out_size)
{
    const float*         dec    = (const float*)d_in[0];
    const float*         enc    = (const float*)d_in[1];
    const unsigned char* mask   = (const unsigned char*)d_in[2];
    const float*         W_h    = (const float*)d_in[3];
    const float*         W_s    = (const float*)d_in[4];
    const float*         w_c    = (const float*)d_in[5];
    const float*         v      = (const float*)d_in[6];
    const float*         b_attn = (const float*)d_in[7];

    float* out  = (float*)d_out;
    float* ctx  = out;
    float* Afin = out + (size_t)B_ * T_ * H_;
    float* loss = Afin + (size_t)B_ * T_ * S_;

    float *pWh = nullptr, *pWs = nullptr;
    cudaGetSymbolAddress((void**)&pWh, g_Wh);
    cudaGetSymbolAddress((void**)&pWs, g_Ws);

    static bool attrDone = false;
    if (!attrDone) {
        cudaFuncSetAttribute(attn_pass<false>,
            cudaFuncAttributeMaxDynamicSharedMemorySize, (int)SMEM_BYTES);
        cudaFuncSetAttribute(attn_pass<true>,
            cudaFuncAttributeMaxDynamicSharedMemorySize, (int)SMEM_BYTES);
        attrDone = true;
    }

    // Wh = enc @ W_h + b_attn  (M=3200, N=256, K=256)
    sgemm64<<<dim3(H_ / 64, (B_ * S_ + 63) / 64), 256>>>(
        enc, W_h, pWh, B_ * S_, H_, H_, b_attn);
    // Ws = dec @ W_s           (M=800)
    sgemm32<<<dim3(H_ / 32, (B_ * T_ + 31) / 32, 1), 256>>>(
        dec, W_s, pWs, B_ * T_, H_, H_, nullptr, 0, 0, 0);

    // Pass 1: A_prelim
    attn_pass<false><<<B_ * (T_ / TT), 128, SMEM_BYTES>>>(
        mask, v, nullptr, nullptr, nullptr);

    // Shifted cumsum over t (also zeroes loss slot)
    cumsum_k<<<(B_ * S_ * 32 + 255) / 256, 256>>>(loss);

    // Pass 2: A_final + cov_loss
    attn_pass<true><<<B_ * (T_ / TT), 128, SMEM_BYTES>>>(
        mask, v, w_c, Afin, loss);

    // context[b] = A_final[b] @ enc[b]
    sgemm32<<<dim3(H_ / 32, (T_ + 31) / 32, B_), 256>>>(
        Afin, enc, ctx, T_, H_, S_, nullptr,
        (long long)T_ * S_, (long long)S_ * H_, (long long)T_ * H_);
}

// round 4
// speedup vs baseline: 1.6487x; 1.6487x over previous
#include <cuda_runtime.h>

// Problem dims (fixed by reference setup_inputs)
constexpr int B_ = 8;
constexpr int T_ = 100;
constexpr int S_ = 400;
constexpr int H_ = 256;

constexpr int TGT = 2;    // t-rows per attn CTA
constexpr int NTH = 416;  // attn threads (13 warps; 400 active s-lanes)

// Scratch (device globals — no allocation allowed)
__device__ float g_Wh [B_ * S_ * H_];   // enc @ W_h + b_attn   [b][s][h]
__device__ float g_WhT[B_ * H_ * S_];   // transposed           [b][h][s]
__device__ float g_Ws [B_ * T_ * H_];   // dec @ W_s
__device__ float g_Apre[B_ * T_ * S_];  // A_prelim
__device__ float g_cov [B_ * T_ * S_];  // shifted cumsum of A_prelim

__device__ __forceinline__ float fast_tanh(float x) {
    float y;
    asm("tanh.approx.f32 %0, %1;" : "=f"(y) : "f"(x));
    return y;
}

// ---------------------------------------------------------------------------
// 64x64-tile SGEMM, 256 threads, 4x4 per thread, K-chunk 16.
// ---------------------------------------------------------------------------
__global__ __launch_bounds__(256) void sgemm64(
    const float* __restrict__ A, const float* __restrict__ Bm,
    float* __restrict__ C, int M, int N, int K,
    const float* __restrict__ bias)
{
    int m0 = blockIdx.y * 64, n0 = blockIdx.x * 64;
    int tid = threadIdx.x;
    int tx = tid & 15, ty = tid >> 4;

    __shared__ float As[16][68];
    __shared__ float Bs[16][68];

    float acc[4][4] = {};

    int lm  = tid >> 2;
    int lk4 = tid & 3;
    int bkr = tid >> 4;
    int bnc = tid & 15;

    for (int k = 0; k < K; k += 16) {
        float4 av = make_float4(0.f, 0.f, 0.f, 0.f);
        int gm = m0 + lm;
        if (gm < M) av = *(const float4*)(A + (size_t)gm * K + k + lk4 * 4);
        As[lk4 * 4 + 0][lm] = av.x;
        As[lk4 * 4 + 1][lm] = av.y;
        As[lk4 * 4 + 2][lm] = av.z;
        As[lk4 * 4 + 3][lm] = av.w;
        float4 bv = *(const float4*)(Bm + (size_t)(k + bkr) * N + n0 + bnc * 4);
        *(float4*)&Bs[bkr][bnc * 4] = bv;
        __syncthreads();
#pragma unroll
        for (int kk = 0; kk < 16; kk++) {
            float4 a = *(float4*)&As[kk][ty * 4];
            float4 b = *(float4*)&Bs[kk][tx * 4];
            acc[0][0] = fmaf(a.x, b.x, acc[0][0]);
            acc[0][1] = fmaf(a.x, b.y, acc[0][1]);
            acc[0][2] = fmaf(a.x, b.z, acc[0][2]);
            acc[0][3] = fmaf(a.x, b.w, acc[0][3]);
            acc[1][0] = fmaf(a.y, b.x, acc[1][0]);
            acc[1][1] = fmaf(a.y, b.y, acc[1][1]);
            acc[1][2] = fmaf(a.y, b.z, acc[1][2]);
            acc[1][3] = fmaf(a.y, b.w, acc[1][3]);
            acc[2][0] = fmaf(a.z, b.x, acc[2][0]);
            acc[2][1] = fmaf(a.z, b.y, acc[2][1]);
            acc[2][2] = fmaf(a.z, b.z, acc[2][2]);
            acc[2][3] = fmaf(a.z, b.w, acc[2][3]);
            acc[3][0] = fmaf(a.w, b.x, acc[3][0]);
            acc[3][1] = fmaf(a.w, b.y, acc[3][1]);
            acc[3][2] = fmaf(a.w, b.z, acc[3][2]);
            acc[3][3] = fmaf(a.w, b.w, acc[3][3]);
        }
        __syncthreads();
    }

#pragma unroll
    for (int i = 0; i < 4; i++) {
        int gm = m0 + ty * 4 + i;
        if (gm < M) {
#pragma unroll
            for (int j = 0; j < 4; j++) {
                int gn = n0 + tx * 4 + j;
                float bi = bias ? bias[gn] : 0.f;
                C[(size_t)gm * N + gn] = acc[i][j] + bi;
            }
        }
    }
}

// ---------------------------------------------------------------------------
// Batched SGEMM, 32x32 tile, 2x2 per thread (Ws + context).
// ---------------------------------------------------------------------------
__global__ __launch_bounds__(256) void sgemm32(
    const float* __restrict__ A, const float* __restrict__ Bm,
    float* __restrict__ C, int M, int N, int K,
    const float* __restrict__ bias,
    long long sA, long long sB, long long sC)
{
    int bz = blockIdx.z;
    A  += (size_t)bz * sA;
    Bm += (size_t)bz * sB;
    C  += (size_t)bz * sC;

    int m0 = blockIdx.y * 32, n0 = blockIdx.x * 32;
    int tid = threadIdx.x;
    int tx = tid & 15, ty = tid >> 4;

    __shared__ float As[32][17];
    __shared__ float Bs[16][33];

    float c00 = 0.f, c01 = 0.f, c10 = 0.f, c11 = 0.f;

    for (int k = 0; k < K; k += 16) {
#pragma unroll
        for (int i = 0; i < 2; i++) {
            int e = tid + i * 256;
            int m = e >> 4, kk = e & 15;
            int gm = m0 + m;
            As[m][kk] = (gm < M) ? A[(size_t)gm * K + k + kk] : 0.f;
            int kk2 = e >> 5, n = e & 31;
            Bs[kk2][n] = Bm[(size_t)(k + kk2) * N + n0 + n];
        }
        __syncthreads();
#pragma unroll
        for (int kk = 0; kk < 16; kk++) {
            float a0 = As[ty][kk], a1 = As[ty + 16][kk];
            float b0 = Bs[kk][tx], b1 = Bs[kk][tx + 16];
            c00 = fmaf(a0, b0, c00);
            c01 = fmaf(a0, b1, c01);
            c10 = fmaf(a1, b0, c10);
            c11 = fmaf(a1, b1, c11);
        }
        __syncthreads();
    }

    float bi0 = bias ? bias[n0 + tx]      : 0.f;
    float bi1 = bias ? bias[n0 + tx + 16] : 0.f;
    if (m0 + ty < M) {
        C[(size_t)(m0 + ty) * N + n0 + tx]      = c00 + bi0;
        C[(size_t)(m0 + ty) * N + n0 + tx + 16] = c01 + bi1;
    }
    if (m0 + ty + 16 < M) {
        C[(size_t)(m0 + ty + 16) * N + n0 + tx]      = c10 + bi0;
        C[(size_t)(m0 + ty + 16) * N + n0 + tx + 16] = c11 + bi1;
    }
}

// ---------------------------------------------------------------------------
// Transpose g_Wh [b][s][h] -> g_WhT [b][h][s]. 32x32 SMEM tiles.
// ---------------------------------------------------------------------------
__global__ __launch_bounds__(256) void transpose_k()
{
    __shared__ float tile[32][33];
    int b  = blockIdx.z;
    int s0 = blockIdx.x * 32, h0 = blockIdx.y * 32;
    int tx = threadIdx.x & 31, ty = threadIdx.x >> 5;  // 32 x 8

    const float* src = g_Wh  + (size_t)b * S_ * H_;
    float*       dst = g_WhT + (size_t)b * H_ * S_;

#pragma unroll
    for (int j = 0; j < 4; j++) {
        int s = s0 + ty + j * 8;
        if (s < S_) tile[ty + j * 8][tx] = src[(size_t)s * H_ + h0 + tx];
    }
    __syncthreads();
#pragma unroll
    for (int j = 0; j < 4; j++) {
        int h = h0 + ty + j * 8;
        int s = s0 + tx;
        if (s < S_) dst[(size_t)h * S_ + s] = tile[tx][ty + j * 8];
    }
}

// ---------------------------------------------------------------------------
// attn_pass v3: lane-per-s over transposed Wh. No shuffles in logits,
// 13 warps/CTA, 10.5 KB SMEM -> 4 CTAs/SM, single wave of 400 CTAs.
// ---------------------------------------------------------------------------
template <bool PASS2>
__global__ __launch_bounds__(NTH) void attn_pass(
    const unsigned char* __restrict__ mask,
    const float* __restrict__ v,
    const float* __restrict__ wc,
    float* __restrict__ AoutParam,
    float* __restrict__ loss)
{
    __shared__ float2 sVW[H_];        // (v[h], wc[h])
    __shared__ float2 sWp[H_];        // (ws_t0[h], ws_t1[h])
    __shared__ float  sE[TGT][S_];
    __shared__ float  sCov[TGT][S_];
    __shared__ float  sRed[16];

    int tid = threadIdx.x;
    int b   = blockIdx.x / (T_ / TGT);
    int t0  = (blockIdx.x % (T_ / TGT)) * TGT;

    const float* ws0 = g_Ws + ((size_t)b * T_ + t0) * H_;
    for (int h = tid; h < H_; h += NTH) {
        sVW[h] = make_float2(v[h], PASS2 ? wc[h] : 0.f);
        sWp[h] = make_float2(ws0[h], ws0[H_ + h]);
    }
    if (PASS2) {
        const float* cv = g_cov + ((size_t)b * T_ + t0) * S_;
        float* flat = &sCov[0][0];
        for (int i = tid; i < TGT * S_; i += NTH) flat[i] = cv[i];
    }
    __syncthreads();

    int s = tid;
    if (s < S_) {
        const float* whp = g_WhT + (size_t)b * H_ * S_ + s;
        float c0 = 0.f, c1 = 0.f;
        if (PASS2) { c0 = sCov[0][s]; c1 = sCov[1][s]; }
        float acc0 = 0.f, acc1 = 0.f;
#pragma unroll 8
        for (int h = 0; h < H_; h++) {
            float  wh = __ldg(whp + (size_t)h * S_);
            float2 vw = sVW[h];
            float2 wp = sWp[h];
            float x0 = wh + wp.x;
            float x1 = wh + wp.y;
            if (PASS2) {
                x0 = fmaf(c0, vw.y, x0);
                x1 = fmaf(c1, vw.y, x1);
            }
            acc0 = fmaf(vw.x, fast_tanh(x0), acc0);
            acc1 = fmaf(vw.x, fast_tanh(x1), acc1);
        }
        bool mk = mask[b * S_ + s] != 0;
        float e0 = fminf(fmaxf(acc0, -30.0f), 30.0f);
        float e1 = fminf(fmaxf(acc1, -30.0f), 30.0f);
        sE[0][s] = mk ? -1e30f : e0;
        sE[1][s] = mk ? -1e30f : e1;
    }
    __syncthreads();

    int lane = tid & 31, wid = tid >> 5;  // 13 warps
    float lossAcc = 0.f;

#pragma unroll
    for (int r = 0; r < TGT; r++) {
        // row max
        float m = (tid < S_) ? sE[r][tid] : -1e30f;
#pragma unroll
        for (int o = 16; o; o >>= 1) m = fmaxf(m, __shfl_xor_sync(0xffffffffu, m, o));
        if (lane == 0) sRed[wid] = m;
        __syncthreads();
        if (wid == 0) {
            float mm = (lane < 13) ? sRed[lane] : -1e30f;
#pragma unroll
            for (int o = 16; o; o >>= 1) mm = fmaxf(mm, __shfl_xor_sync(0xffffffffu, mm, o));
            if (lane == 0) sRed[14] = mm;
        }
        __syncthreads();
        float rowMax = sRed[14];

        // exp + sum
        float ex = (tid < S_) ? __expf(sE[r][tid] - rowMax) : 0.f;
        float sum = ex;
#pragma unroll
        for (int o = 16; o; o >>= 1) sum += __shfl_xor_sync(0xffffffffu, sum, o);
        if (lane == 0) sRed[wid] = sum;
        __syncthreads();
        if (wid == 0) {
            float ss = (lane < 13) ? sRed[lane] : 0.f;
#pragma unroll
            for (int o = 16; o; o >>= 1) ss += __shfl_xor_sync(0xffffffffu, ss, o);
            if (lane == 0) sRed[15] = ss;
        }
        __syncthreads();
        float inv = 1.0f / fmaxf(sRed[15], 1e-30f);

        if (tid < S_) {
            float a = ex * inv;
            size_t rowOff = ((size_t)b * T_ + t0 + r) * S_;
            (PASS2 ? AoutParam : g_Apre)[rowOff + tid] = a;
            if (PASS2) lossAcc += fminf(a, sCov[r][tid]);
        }
        __syncthreads();
    }

    if (PASS2) {
#pragma unroll
        for (int o = 16; o; o >>= 1) lossAcc += __shfl_xor_sync(0xffffffffu, lossAcc, o);
        if (lane == 0) sRed[wid] = lossAcc;
        __syncthreads();
        if (tid == 0) {
            float p = 0.f;
#pragma unroll
            for (int i = 0; i < 13; i++) p += sRed[i];
            atomicAdd(loss, p * (1.0f / (B_ * T_)));
        }
    }
}

// ---------------------------------------------------------------------------
// cumsum: one warp per (b,s); 4 up-front loads + 4 warp scans.
// ---------------------------------------------------------------------------
__global__ __launch_bounds__(256) void cumsum_k(float* __restrict__ loss)
{
    int gt = blockIdx.x * blockDim.x + threadIdx.x;
    int gw = gt >> 5;
    int lane = gt & 31;
    if (gt == 0) *loss = 0.f;
    if (gw >= B_ * S_) return;
    int b = gw / S_, s = gw % S_;
    const float* src = g_Apre + (size_t)b * T_ * S_ + s;
    float*       dst = g_cov  + (size_t)b * T_ * S_ + s;

    float vals[4];
#pragma unroll
    for (int k = 0; k < 4; k++) {
        int t = k * 32 + lane;
        vals[k] = (t < T_) ? src[(size_t)t * S_] : 0.f;
    }
    float run = 0.f;
#pragma unroll
    for (int k = 0; k < 4; k++) {
        float x = vals[k];
#pragma unroll
        for (int off = 1; off < 32; off <<= 1) {
            float y = __shfl_up_sync(0xffffffffu, x, off);
            if (lane >= off) x += y;
        }
        int t = k * 32 + lane;
        if (t < T_) dst[(size_t)t * S_] = run + (x - vals[k]);
        run += __shfl_sync(0xffffffffu, x, 31);
    }
}

// ---------------------------------------------------------------------------
extern "C" void kernel_launch(void* const* d_in, const int* in_sizes, int n_in,
                              void* d_out, int out_size)
{
    const float*         dec    = (const float*)d_in[0];
    const float*         enc    = (const float*)d_in[1];
    const unsigned char* mask   = (const unsigned char*)d_in[2];
    const float*         W_h    = (const float*)d_in[3];
    const float*         W_s    = (const float*)d_in[4];
    const float*         w_c    = (const float*)d_in[5];
    const float*         v      = (const float*)d_in[6];
    const float*         b_attn = (const float*)d_in[7];

    float* out  = (float*)d_out;
    float* ctx  = out;
    float* Afin = out + (size_t)B_ * T_ * H_;
    float* loss = Afin + (size_t)B_ * T_ * S_;

    float *pWh = nullptr, *pWs = nullptr;
    cudaGetSymbolAddress((void**)&pWh, g_Wh);
    cudaGetSymbolAddress((void**)&pWs, g_Ws);

    // Wh = enc @ W_h + b_attn  (M=3200, N=256, K=256)
    sgemm64<<<dim3(H_ / 64, (B_ * S_ + 63) / 64), 256>>>(
        enc, W_h, pWh, B_ * S_, H_, H_, b_attn);
    // Ws = dec @ W_s           (M=800)
    sgemm32<<<dim3(H_ / 32, (B_ * T_ + 31) / 32, 1), 256>>>(
        dec, W_s, pWs, B_ * T_, H_, H_, nullptr, 0, 0, 0);
    // WhT = transpose(Wh)
    transpose_k<<<dim3((S_ + 31) / 32, H_ / 32, B_), 256>>>();

    // Pass 1: A_prelim
    attn_pass<false><<<B_ * (T_ / TGT), NTH>>>(mask, v, nullptr, nullptr, nullptr);

    // Shifted cumsum over t (also zeroes loss slot)
    cumsum_k<<<(B_ * S_ * 32 + 255) / 256, 256>>>(loss);

    // Pass 2: A_final + cov_loss
    attn_pass<true><<<B_ * (T_ / TGT), NTH>>>(mask, v, w_c, Afin, loss);

    // context[b] = A_final[b] @ enc[b]
    sgemm32<<<dim3(H_ / 32, (T_ + 31) / 32, B_), 256>>>(
        Afin, enc, ctx, T_, H_, S_, nullptr,
        (long long)T_ * S_, (long long)S_ * H_, (long long)T_ * H_);
}

// round 5
// speedup vs baseline: 1.6733x; 1.0149x over previous
#include <cuda_runtime.h>

// Problem dims (fixed by reference setup_inputs)
constexpr int B_ = 8;
constexpr int T_ = 100;
constexpr int S_ = 400;
constexpr int H_ = 256;

constexpr int TGT = 2;    // t-rows per attn CTA
constexpr int NTH = 416;  // attn threads (13 warps; 400 active s-lanes)

// Scratch (device globals — no allocation allowed)
__device__ float g_Wh [B_ * S_ * H_];   // enc @ W_h + b_attn   [b][s][h]
__device__ float g_WhT[B_ * H_ * S_];   // transposed           [b][h][s]
__device__ float g_Ws [B_ * T_ * H_];   // dec @ W_s
__device__ float g_Apre[B_ * T_ * S_];  // A_prelim
__device__ float g_cov [B_ * T_ * S_];  // shifted cumsum of A_prelim

__device__ __forceinline__ float fast_tanh(float x) {
    float y;
    asm("tanh.approx.f32 %0, %1;" : "=f"(y) : "f"(x));
    return y;
}

// ---------------------------------------------------------------------------
// 64x32-tile SGEMM, 256 threads, 2x4 per thread, K-chunk 16.
// Grid: (N/32, ceil(M/64)). Better CTA balance than 64x64 at these sizes.
// ---------------------------------------------------------------------------
__global__ __launch_bounds__(256) void sgemm64x32(
    const float* __restrict__ A, const float* __restrict__ Bm,
    float* __restrict__ C, int M, int N, int K,
    const float* __restrict__ bias)
{
    int m0 = blockIdx.y * 64, n0 = blockIdx.x * 32;
    int tid = threadIdx.x;
    int tx = tid & 7;        // 8 groups of 4 cols
    int ty = tid >> 3;       // 32 rows of 2 m

    __shared__ float As[16][68];   // [k][m]
    __shared__ float Bs[16][36];   // [k][n]

    float acc[2][4] = {};

    int lm  = tid >> 2;      // 0..63 A row
    int lk4 = tid & 3;       // float4 idx in k-chunk
    int bkr = tid >> 4;      // 0..15 B k-row
    int bnc = tid & 15;      // 16 groups of 2 cols

    for (int k = 0; k < K; k += 16) {
        float4 av = make_float4(0.f, 0.f, 0.f, 0.f);
        int gm = m0 + lm;
        if (gm < M) av = *(const float4*)(A + (size_t)gm * K + k + lk4 * 4);
        As[lk4 * 4 + 0][lm] = av.x;
        As[lk4 * 4 + 1][lm] = av.y;
        As[lk4 * 4 + 2][lm] = av.z;
        As[lk4 * 4 + 3][lm] = av.w;
        float2 bv = *(const float2*)(Bm + (size_t)(k + bkr) * N + n0 + bnc * 2);
        Bs[bkr][bnc * 2 + 0] = bv.x;
        Bs[bkr][bnc * 2 + 1] = bv.y;
        __syncthreads();
#pragma unroll
        for (int kk = 0; kk < 16; kk++) {
            float2 a = *(float2*)&As[kk][ty * 2];
            float4 b = *(float4*)&Bs[kk][tx * 4];
            acc[0][0] = fmaf(a.x, b.x, acc[0][0]);
            acc[0][1] = fmaf(a.x, b.y, acc[0][1]);
            acc[0][2] = fmaf(a.x, b.z, acc[0][2]);
            acc[0][3] = fmaf(a.x, b.w, acc[0][3]);
            acc[1][0] = fmaf(a.y, b.x, acc[1][0]);
            acc[1][1] = fmaf(a.y, b.y, acc[1][1]);
            acc[1][2] = fmaf(a.y, b.z, acc[1][2]);
            acc[1][3] = fmaf(a.y, b.w, acc[1][3]);
        }
        __syncthreads();
    }

    float bi[4];
#pragma unroll
    for (int j = 0; j < 4; j++) bi[j] = bias ? bias[n0 + tx * 4 + j] : 0.f;
#pragma unroll
    for (int i = 0; i < 2; i++) {
        int gm = m0 + ty * 2 + i;
        if (gm < M) {
#pragma unroll
            for (int j = 0; j < 4; j++)
                C[(size_t)gm * N + n0 + tx * 4 + j] = acc[i][j] + bi[j];
        }
    }
}

// ---------------------------------------------------------------------------
// Batched SGEMM, 32x32 tile, 2x2 per thread (context).
// ---------------------------------------------------------------------------
__global__ __launch_bounds__(256) void sgemm32(
    const float* __restrict__ A, const float* __restrict__ Bm,
    float* __restrict__ C, int M, int N, int K,
    const float* __restrict__ bias,
    long long sA, long long sB, long long sC)
{
    int bz = blockIdx.z;
    A  += (size_t)bz * sA;
    Bm += (size_t)bz * sB;
    C  += (size_t)bz * sC;

    int m0 = blockIdx.y * 32, n0 = blockIdx.x * 32;
    int tid = threadIdx.x;
    int tx = tid & 15, ty = tid >> 4;

    __shared__ float As[32][17];
    __shared__ float Bs[16][33];

    float c00 = 0.f, c01 = 0.f, c10 = 0.f, c11 = 0.f;

    for (int k = 0; k < K; k += 16) {
#pragma unroll
        for (int i = 0; i < 2; i++) {
            int e = tid + i * 256;
            int m = e >> 4, kk = e & 15;
            int gm = m0 + m;
            As[m][kk] = (gm < M) ? A[(size_t)gm * K + k + kk] : 0.f;
            int kk2 = e >> 5, n = e & 31;
            Bs[kk2][n] = Bm[(size_t)(k + kk2) * N + n0 + n];
        }
        __syncthreads();
#pragma unroll
        for (int kk = 0; kk < 16; kk++) {
            float a0 = As[ty][kk], a1 = As[ty + 16][kk];
            float b0 = Bs[kk][tx], b1 = Bs[kk][tx + 16];
            c00 = fmaf(a0, b0, c00);
            c01 = fmaf(a0, b1, c01);
            c10 = fmaf(a1, b0, c10);
            c11 = fmaf(a1, b1, c11);
        }
        __syncthreads();
    }

    float bi0 = bias ? bias[n0 + tx]      : 0.f;
    float bi1 = bias ? bias[n0 + tx + 16] : 0.f;
    if (m0 + ty < M) {
        C[(size_t)(m0 + ty) * N + n0 + tx]      = c00 + bi0;
        C[(size_t)(m0 + ty) * N + n0 + tx + 16] = c01 + bi1;
    }
    if (m0 + ty + 16 < M) {
        C[(size_t)(m0 + ty + 16) * N + n0 + tx]      = c10 + bi0;
        C[(size_t)(m0 + ty + 16) * N + n0 + tx + 16] = c11 + bi1;
    }
}

// ---------------------------------------------------------------------------
// Transpose g_Wh [b][s][h] -> g_WhT [b][h][s]. 32x32 SMEM tiles.
// ---------------------------------------------------------------------------
__global__ __launch_bounds__(256) void transpose_k()
{
    __shared__ float tile[32][33];
    int b  = blockIdx.z;
    int s0 = blockIdx.x * 32, h0 = blockIdx.y * 32;
    int tx = threadIdx.x & 31, ty = threadIdx.x >> 5;  // 32 x 8

    const float* src = g_Wh  + (size_t)b * S_ * H_;
    float*       dst = g_WhT + (size_t)b * H_ * S_;

#pragma unroll
    for (int j = 0; j < 4; j++) {
        int s = s0 + ty + j * 8;
        if (s < S_) tile[ty + j * 8][tx] = src[(size_t)s * H_ + h0 + tx];
    }
    __syncthreads();
#pragma unroll
    for (int j = 0; j < 4; j++) {
        int h = h0 + ty + j * 8;
        int s = s0 + tx;
        if (s < S_) dst[(size_t)h * S_ + s] = tile[tx][ty + j * 8];
    }
}

// ---------------------------------------------------------------------------
// attn_pass v4: lane-per-s over transposed Wh; params packed as one float4
// per h -> single LDS.128 in the inner loop. 13 warps/CTA, ~10.5 KB SMEM.
// ---------------------------------------------------------------------------
template <bool PASS2>
__global__ __launch_bounds__(NTH) void attn_pass(
    const unsigned char* __restrict__ mask,
    const float* __restrict__ v,
    const float* __restrict__ wc,
    float* __restrict__ AoutParam,
    float* __restrict__ loss)
{
    __shared__ float4 sPack[H_];      // (v, wc, ws_t0, ws_t1)
    __shared__ float  sE[TGT][S_];
    __shared__ float  sCov[TGT][S_];
    __shared__ float  sRed[16];

    int tid = threadIdx.x;
    int b   = blockIdx.x / (T_ / TGT);
    int t0  = (blockIdx.x % (T_ / TGT)) * TGT;

    const float* ws0 = g_Ws + ((size_t)b * T_ + t0) * H_;
    for (int h = tid; h < H_; h += NTH) {
        sPack[h] = make_float4(v[h], PASS2 ? wc[h] : 0.f, ws0[h], ws0[H_ + h]);
    }
    if (PASS2) {
        const float* cv = g_cov + ((size_t)b * T_ + t0) * S_;
        float* flat = &sCov[0][0];
        for (int i = tid; i < TGT * S_; i += NTH) flat[i] = cv[i];
    }
    __syncthreads();

    int s = tid;
    if (s < S_) {
        const float* whp = g_WhT + (size_t)b * H_ * S_ + s;
        bool mk = mask[b * S_ + s] != 0;
        float c0 = 0.f, c1 = 0.f;
        if (PASS2) { c0 = sCov[0][s]; c1 = sCov[1][s]; }
        float acc0 = 0.f, acc1 = 0.f;
#pragma unroll 8
        for (int h = 0; h < H_; h++) {
            float  wh = __ldg(whp + (size_t)h * S_);
            float4 p  = sPack[h];
            float x0 = wh + p.z;
            float x1 = wh + p.w;
            if (PASS2) {
                x0 = fmaf(c0, p.y, x0);
                x1 = fmaf(c1, p.y, x1);
            }
            acc0 = fmaf(p.x, fast_tanh(x0), acc0);
            acc1 = fmaf(p.x, fast_tanh(x1), acc1);
        }
        float e0 = fminf(fmaxf(acc0, -30.0f), 30.0f);
        float e1 = fminf(fmaxf(acc1, -30.0f), 30.0f);
        sE[0][s] = mk ? -1e30f : e0;
        sE[1][s] = mk ? -1e30f : e1;
    }
    __syncthreads();

    int lane = tid & 31, wid = tid >> 5;  // 13 warps
    float lossAcc = 0.f;

#pragma unroll
    for (int r = 0; r < TGT; r++) {
        float m = (tid < S_) ? sE[r][tid] : -1e30f;
#pragma unroll
        for (int o = 16; o; o >>= 1) m = fmaxf(m, __shfl_xor_sync(0xffffffffu, m, o));
        if (lane == 0) sRed[wid] = m;
        __syncthreads();
        if (wid == 0) {
            float mm = (lane < 13) ? sRed[lane] : -1e30f;
#pragma unroll
            for (int o = 16; o; o >>= 1) mm = fmaxf(mm, __shfl_xor_sync(0xffffffffu, mm, o));
            if (lane == 0) sRed[14] = mm;
        }
        __syncthreads();
        float rowMax = sRed[14];

        float ex = (tid < S_) ? __expf(sE[r][tid] - rowMax) : 0.f;
        float sum = ex;
#pragma unroll
        for (int o = 16; o; o >>= 1) sum += __shfl_xor_sync(0xffffffffu, sum, o);
        if (lane == 0) sRed[wid] = sum;
        __syncthreads();
        if (wid == 0) {
            float ss = (lane < 13) ? sRed[lane] : 0.f;
#pragma unroll
            for (int o = 16; o; o >>= 1) ss += __shfl_xor_sync(0xffffffffu, ss, o);
            if (lane == 0) sRed[15] = ss;
        }
        __syncthreads();
        float inv = 1.0f / fmaxf(sRed[15], 1e-30f);

        if (tid < S_) {
            float a = ex * inv;
            size_t rowOff = ((size_t)b * T_ + t0 + r) * S_;
            (PASS2 ? AoutParam : g_Apre)[rowOff + tid] = a;
            if (PASS2) lossAcc += fminf(a, sCov[r][tid]);
        }
        __syncthreads();
    }

    if (PASS2) {
#pragma unroll
        for (int o = 16; o; o >>= 1) lossAcc += __shfl_xor_sync(0xffffffffu, lossAcc, o);
        if (lane == 0) sRed[wid] = lossAcc;
        __syncthreads();
        if (tid == 0) {
            float p = 0.f;
#pragma unroll
            for (int i = 0; i < 13; i++) p += sRed[i];
            atomicAdd(loss, p * (1.0f / (B_ * T_)));
        }
    }
}

// ---------------------------------------------------------------------------
// cumsum: one warp per (b,s); 4 up-front loads + 4 warp scans.
// ---------------------------------------------------------------------------
__global__ __launch_bounds__(256) void cumsum_k(float* __restrict__ loss)
{
    int gt = blockIdx.x * blockDim.x + threadIdx.x;
    int gw = gt >> 5;
    int lane = gt & 31;
    if (gt == 0) *loss = 0.f;
    if (gw >= B_ * S_) return;
    int b = gw / S_, s = gw % S_;
    const float* src = g_Apre + (size_t)b * T_ * S_ + s;
    float*       dst = g_cov  + (size_t)b * T_ * S_ + s;

    float vals[4];
#pragma unroll
    for (int k = 0; k < 4; k++) {
        int t = k * 32 + lane;
        vals[k] = (t < T_) ? src[(size_t)t * S_] : 0.f;
    }
    float run = 0.f;
#pragma unroll
    for (int k = 0; k < 4; k++) {
        float x = vals[k];
#pragma unroll
        for (int off = 1; off < 32; off <<= 1) {
            float y = __shfl_up_sync(0xffffffffu, x, off);
            if (lane >= off) x += y;
        }
        int t = k * 32 + lane;
        if (t < T_) dst[(size_t)t * S_] = run + (x - vals[k]);
        run += __shfl_sync(0xffffffffu, x, 31);
    }
}

// ---------------------------------------------------------------------------
extern "C" void kernel_launch(void* const* d_in, const int* in_sizes, int n_in,
                              void* d_out, int out_size)
{
    const float*         dec    = (const float*)d_in[0];
    const float*         enc    = (const float*)d_in[1];
    const unsigned char* mask   = (const unsigned char*)d_in[2];
    const float*         W_h    = (const float*)d_in[3];
    const float*         W_s    = (const float*)d_in[4];
    const float*         w_c    = (const float*)d_in[5];
    const float*         v      = (const float*)d_in[6];
    const float*         b_attn = (const float*)d_in[7];

    float* out  = (float*)d_out;
    float* ctx  = out;
    float* Afin = out + (size_t)B_ * T_ * H_;
    float* loss = Afin + (size_t)B_ * T_ * S_;

    float *pWh = nullptr, *pWs = nullptr;
    cudaGetSymbolAddress((void**)&pWh, g_Wh);
    cudaGetSymbolAddress((void**)&pWs, g_Ws);

    // Wh = enc @ W_h + b_attn  (M=3200, N=256, K=256) — 64x32 tiles, 400 CTAs
    sgemm64x32<<<dim3(H_ / 32, (B_ * S_ + 63) / 64), 256>>>(
        enc, W_h, pWh, B_ * S_, H_, H_, b_attn);
    // Ws = dec @ W_s           (M=800) — 104 CTAs
    sgemm64x32<<<dim3(H_ / 32, (B_ * T_ + 63) / 64), 256>>>(
        dec, W_s, pWs, B_ * T_, H_, H_, nullptr);
    // WhT = transpose(Wh)
    transpose_k<<<dim3((S_ + 31) / 32, H_ / 32, B_), 256>>>();

    // Pass 1: A_prelim
    attn_pass<false><<<B_ * (T_ / TGT), NTH>>>(mask, v, nullptr, nullptr, nullptr);

    // Shifted cumsum over t (also zeroes loss slot)
    cumsum_k<<<(B_ * S_ * 32 + 255) / 256, 256>>>(loss);

    // Pass 2: A_final + cov_loss
    attn_pass<true><<<B_ * (T_ / TGT), NTH>>>(mask, v, w_c, Afin, loss);

    // context[b] = A_final[b] @ enc[b]
    sgemm32<<<dim3(H_ / 32, (T_ + 31) / 32, B_), 256>>>(
        Afin, enc, ctx, T_, H_, S_, nullptr,
        (long long)T_ * S_, (long long)S_ * H_, (long long)T_ * H_);
}

// round 6
// speedup vs baseline: 1.8722x; 1.1188x over previous
#include <cuda_runtime.h>

// Problem dims (fixed by reference setup_inputs)
constexpr int B_ = 8;
constexpr int T_ = 100;
constexpr int S_ = 400;
constexpr int H_ = 256;

constexpr int TGT = 2;    // t-rows per attn CTA
constexpr int NTH = 416;  // attn threads (13 warps; 400 active s-lanes)

// Scratch (device globals — no allocation allowed)
__device__ float g_WhT[B_ * H_ * S_];   // (enc @ W_h + b_attn)^T : [b][h][s]
__device__ float g_Ws [B_ * T_ * H_];   // dec @ W_s
__device__ float g_Apre[B_ * T_ * S_];  // A_prelim
__device__ float g_cov [B_ * T_ * S_];  // shifted cumsum of A_prelim

__device__ __forceinline__ float fast_tanh(float x) {
    float y;
    asm("tanh.approx.f32 %0, %1;" : "=f"(y) : "f"(x));
    return y;
}

// ---------------------------------------------------------------------------
// 64x32-tile SGEMM producing TRANSPOSED output into g_WhT.
// C logical = A[M,K] @ Bm[K,N] + bias ; stored as WhT[b][n][s] with
// m = b*S_ + s. M=3200 -> 50 m-tiles exactly. 256 thr, 2x4 per thread.
// ---------------------------------------------------------------------------
__global__ __launch_bounds__(256) void sgemmWhT(
    const float* __restrict__ A, const float* __restrict__ Bm,
    const float* __restrict__ bias)
{
    constexpr int K = H_, N = H_;
    int m0 = blockIdx.y * 64, n0 = blockIdx.x * 32;
    int tid = threadIdx.x;
    int tx = tid & 7;        // 8 groups of 4 cols
    int ty = tid >> 3;       // 32 rows of 2 m

    __shared__ float As[16][68];   // [k][m]
    __shared__ float Bs[16][36];   // [k][n]
    __shared__ float Ts[32][65];   // transposed tile [h][s]

    float acc[2][4] = {};

    int lm  = tid >> 2;      // 0..63 A row
    int lk4 = tid & 3;       // float4 idx in k-chunk
    int bkr = tid >> 4;      // 0..15 B k-row
    int bnc = tid & 15;      // 16 groups of 2 cols

    for (int k = 0; k < K; k += 16) {
        float4 av = *(const float4*)(A + (size_t)(m0 + lm) * K + k + lk4 * 4);
        As[lk4 * 4 + 0][lm] = av.x;
        As[lk4 * 4 + 1][lm] = av.y;
        As[lk4 * 4 + 2][lm] = av.z;
        As[lk4 * 4 + 3][lm] = av.w;
        float2 bv = *(const float2*)(Bm + (size_t)(k + bkr) * N + n0 + bnc * 2);
        Bs[bkr][bnc * 2 + 0] = bv.x;
        Bs[bkr][bnc * 2 + 1] = bv.y;
        __syncthreads();
#pragma unroll
        for (int kk = 0; kk < 16; kk++) {
            float2 a = *(float2*)&As[kk][ty * 2];
            float4 b = *(float4*)&Bs[kk][tx * 4];
            acc[0][0] = fmaf(a.x, b.x, acc[0][0]);
            acc[0][1] = fmaf(a.x, b.y, acc[0][1]);
            acc[0][2] = fmaf(a.x, b.z, acc[0][2]);
            acc[0][3] = fmaf(a.x, b.w, acc[0][3]);
            acc[1][0] = fmaf(a.y, b.x, acc[1][0]);
            acc[1][1] = fmaf(a.y, b.y, acc[1][1]);
            acc[1][2] = fmaf(a.y, b.z, acc[1][2]);
            acc[1][3] = fmaf(a.y, b.w, acc[1][3]);
        }
        __syncthreads();
    }

    // Epilogue: bias add, transpose via SMEM, coalesced store to WhT.
#pragma unroll
    for (int j = 0; j < 4; j++) {
        float bi = bias[n0 + tx * 4 + j];
#pragma unroll
        for (int i = 0; i < 2; i++)
            Ts[tx * 4 + j][ty * 2 + i] = acc[i][j] + bi;
    }
    __syncthreads();
#pragma unroll
    for (int k = 0; k < 8; k++) {
        int e  = tid + 256 * k;
        int h  = e >> 6;          // 0..31
        int sl = e & 63;
        int m  = m0 + sl;
        int b  = m / S_;
        int s  = m - b * S_;
        g_WhT[(size_t)b * H_ * S_ + (size_t)(n0 + h) * S_ + s] = Ts[h][sl];
    }
}

// ---------------------------------------------------------------------------
// 64x32-tile SGEMM, normal row-major output (Ws).
// ---------------------------------------------------------------------------
__global__ __launch_bounds__(256) void sgemm64x32(
    const float* __restrict__ A, const float* __restrict__ Bm,
    float* __restrict__ C, int M, int N, int K)
{
    int m0 = blockIdx.y * 64, n0 = blockIdx.x * 32;
    int tid = threadIdx.x;
    int tx = tid & 7;
    int ty = tid >> 3;

    __shared__ float As[16][68];
    __shared__ float Bs[16][36];

    float acc[2][4] = {};

    int lm  = tid >> 2;
    int lk4 = tid & 3;
    int bkr = tid >> 4;
    int bnc = tid & 15;

    for (int k = 0; k < K; k += 16) {
        float4 av = make_float4(0.f, 0.f, 0.f, 0.f);
        int gm = m0 + lm;
        if (gm < M) av = *(const float4*)(A + (size_t)gm * K + k + lk4 * 4);
        As[lk4 * 4 + 0][lm] = av.x;
        As[lk4 * 4 + 1][lm] = av.y;
        As[lk4 * 4 + 2][lm] = av.z;
        As[lk4 * 4 + 3][lm] = av.w;
        float2 bv = *(const float2*)(Bm + (size_t)(k + bkr) * N + n0 + bnc * 2);
        Bs[bkr][bnc * 2 + 0] = bv.x;
        Bs[bkr][bnc * 2 + 1] = bv.y;
        __syncthreads();
#pragma unroll
        for (int kk = 0; kk < 16; kk++) {
            float2 a = *(float2*)&As[kk][ty * 2];
            float4 b = *(float4*)&Bs[kk][tx * 4];
            acc[0][0] = fmaf(a.x, b.x, acc[0][0]);
            acc[0][1] = fmaf(a.x, b.y, acc[0][1]);
            acc[0][2] = fmaf(a.x, b.z, acc[0][2]);
            acc[0][3] = fmaf(a.x, b.w, acc[0][3]);
            acc[1][0] = fmaf(a.y, b.x, acc[1][0]);
            acc[1][1] = fmaf(a.y, b.y, acc[1][1]);
            acc[1][2] = fmaf(a.y, b.z, acc[1][2]);
            acc[1][3] = fmaf(a.y, b.w, acc[1][3]);
        }
        __syncthreads();
    }

#pragma unroll
    for (int i = 0; i < 2; i++) {
        int gm = m0 + ty * 2 + i;
        if (gm < M) {
#pragma unroll
            for (int j = 0; j < 4; j++)
                C[(size_t)gm * N + n0 + tx * 4 + j] = acc[i][j];
        }
    }
}

// ---------------------------------------------------------------------------
// Batched SGEMM, 32x32 tile, 2x2 per thread (context).
// ---------------------------------------------------------------------------
__global__ __launch_bounds__(256) void sgemm32(
    const float* __restrict__ A, const float* __restrict__ Bm,
    float* __restrict__ C, int M, int N, int K,
    long long sA, long long sB, long long sC)
{
    int bz = blockIdx.z;
    A  += (size_t)bz * sA;
    Bm += (size_t)bz * sB;
    C  += (size_t)bz * sC;

    int m0 = blockIdx.y * 32, n0 = blockIdx.x * 32;
    int tid = threadIdx.x;
    int tx = tid & 15, ty = tid >> 4;

    __shared__ float As[32][17];
    __shared__ float Bs[16][33];

    float c00 = 0.f, c01 = 0.f, c10 = 0.f, c11 = 0.f;

    for (int k = 0; k < K; k += 16) {
#pragma unroll
        for (int i = 0; i < 2; i++) {
            int e = tid + i * 256;
            int m = e >> 4, kk = e & 15;
            int gm = m0 + m;
            As[m][kk] = (gm < M) ? A[(size_t)gm * K + k + kk] : 0.f;
            int kk2 = e >> 5, n = e & 31;
            Bs[kk2][n] = Bm[(size_t)(k + kk2) * N + n0 + n];
        }
        __syncthreads();
#pragma unroll
        for (int kk = 0; kk < 16; kk++) {
            float a0 = As[ty][kk], a1 = As[ty + 16][kk];
            float b0 = Bs[kk][tx], b1 = Bs[kk][tx + 16];
            c00 = fmaf(a0, b0, c00);
            c01 = fmaf(a0, b1, c01);
            c10 = fmaf(a1, b0, c10);
            c11 = fmaf(a1, b1, c11);
        }
        __syncthreads();
    }

    if (m0 + ty < M) {
        C[(size_t)(m0 + ty) * N + n0 + tx]      = c00;
        C[(size_t)(m0 + ty) * N + n0 + tx + 16] = c01;
    }
    if (m0 + ty + 16 < M) {
        C[(size_t)(m0 + ty + 16) * N + n0 + tx]      = c10;
        C[(size_t)(m0 + ty + 16) * N + n0 + tx + 16] = c11;
    }
}

// ---------------------------------------------------------------------------
// attn_pass (R4-proven inner loop): lane-per-s over WhT, two independent
// small LDS streams (sVW, sWp). 13 warps/CTA.
// ---------------------------------------------------------------------------
template <bool PASS2>
__global__ __launch_bounds__(NTH) void attn_pass(
    const unsigned char* __restrict__ mask,
    const float* __restrict__ v,
    const float* __restrict__ wc,
    float* __restrict__ AoutParam,
    float* __restrict__ loss)
{
    __shared__ float2 sVW[H_];        // (v[h], wc[h])
    __shared__ float2 sWp[H_];        // (ws_t0[h], ws_t1[h])
    __shared__ float  sE[TGT][S_];
    __shared__ float  sCov[TGT][S_];
    __shared__ float  sRed[16];

    int tid = threadIdx.x;
    int b   = blockIdx.x / (T_ / TGT);
    int t0  = (blockIdx.x % (T_ / TGT)) * TGT;

    const float* ws0 = g_Ws + ((size_t)b * T_ + t0) * H_;
    for (int h = tid; h < H_; h += NTH) {
        sVW[h] = make_float2(v[h], PASS2 ? wc[h] : 0.f);
        sWp[h] = make_float2(ws0[h], ws0[H_ + h]);
    }
    if (PASS2) {
        const float* cv = g_cov + ((size_t)b * T_ + t0) * S_;
        float* flat = &sCov[0][0];
        for (int i = tid; i < TGT * S_; i += NTH) flat[i] = cv[i];
    }
    __syncthreads();

    int s = tid;
    if (s < S_) {
        const float* whp = g_WhT + (size_t)b * H_ * S_ + s;
        bool mk = mask[b * S_ + s] != 0;
        float c0 = 0.f, c1 = 0.f;
        if (PASS2) { c0 = sCov[0][s]; c1 = sCov[1][s]; }
        float acc0 = 0.f, acc1 = 0.f;
#pragma unroll 8
        for (int h = 0; h < H_; h++) {
            float  wh = __ldg(whp + (size_t)h * S_);
            float2 vw = sVW[h];
            float2 wp = sWp[h];
            float x0 = wh + wp.x;
            float x1 = wh + wp.y;
            if (PASS2) {
                x0 = fmaf(c0, vw.y, x0);
                x1 = fmaf(c1, vw.y, x1);
            }
            acc0 = fmaf(vw.x, fast_tanh(x0), acc0);
            acc1 = fmaf(vw.x, fast_tanh(x1), acc1);
        }
        float e0 = fminf(fmaxf(acc0, -30.0f), 30.0f);
        float e1 = fminf(fmaxf(acc1, -30.0f), 30.0f);
        sE[0][s] = mk ? -1e30f : e0;
        sE[1][s] = mk ? -1e30f : e1;
    }
    __syncthreads();

    int lane = tid & 31, wid = tid >> 5;  // 13 warps
    float lossAcc = 0.f;

#pragma unroll
    for (int r = 0; r < TGT; r++) {
        float m = (tid < S_) ? sE[r][tid] : -1e30f;
#pragma unroll
        for (int o = 16; o; o >>= 1) m = fmaxf(m, __shfl_xor_sync(0xffffffffu, m, o));
        if (lane == 0) sRed[wid] = m;
        __syncthreads();
        if (wid == 0) {
            float mm = (lane < 13) ? sRed[lane] : -1e30f;
#pragma unroll
            for (int o = 16; o; o >>= 1) mm = fmaxf(mm, __shfl_xor_sync(0xffffffffu, mm, o));
            if (lane == 0) sRed[14] = mm;
        }
        __syncthreads();
        float rowMax = sRed[14];

        float ex = (tid < S_) ? __expf(sE[r][tid] - rowMax) : 0.f;
        float sum = ex;
#pragma unroll
        for (int o = 16; o; o >>= 1) sum += __shfl_xor_sync(0xffffffffu, sum, o);
        if (lane == 0) sRed[wid] = sum;
        __syncthreads();
        if (wid == 0) {
            float ss = (lane < 13) ? sRed[lane] : 0.f;
#pragma unroll
            for (int o = 16; o; o >>= 1) ss += __shfl_xor_sync(0xffffffffu, ss, o);
            if (lane == 0) sRed[15] = ss;
        }
        __syncthreads();
        float inv = 1.0f / fmaxf(sRed[15], 1e-30f);

        if (tid < S_) {
            float a = ex * inv;
            size_t rowOff = ((size_t)b * T_ + t0 + r) * S_;
            (PASS2 ? AoutParam : g_Apre)[rowOff + tid] = a;
            if (PASS2) lossAcc += fminf(a, sCov[r][tid]);
        }
        __syncthreads();
    }

    if (PASS2) {
#pragma unroll
        for (int o = 16; o; o >>= 1) lossAcc += __shfl_xor_sync(0xffffffffu, lossAcc, o);
        if (lane == 0) sRed[wid] = lossAcc;
        __syncthreads();
        if (tid == 0) {
            float p = 0.f;
#pragma unroll
            for (int i = 0; i < 13; i++) p += sRed[i];
            atomicAdd(loss, p * (1.0f / (B_ * T_)));
        }
    }
}

// ---------------------------------------------------------------------------
// cumsum v4: CTA = (b, 64 s-lanes); 256 threads = 64 s x 4 t-groups of 25.
// Fully coalesced loads/stores, 25-deep MLP, smem 2-level exclusive scan.
// ---------------------------------------------------------------------------
__global__ __launch_bounds__(256) void cumsum_k(float* __restrict__ loss)
{
    constexpr int TSEG = 25;
    __shared__ float tot[4][64];

    if (blockIdx.x == 0 && blockIdx.y == 0 && threadIdx.x == 0) *loss = 0.f;

    int g  = threadIdx.x >> 6;       // t-group 0..3
    int sl = threadIdx.x & 63;
    int s  = blockIdx.x * 64 + sl;
    int b  = blockIdx.y;
    bool act = (s < S_);

    size_t base = (size_t)b * T_ * S_ + s;
    float vals[TSEG];
    if (act) {
#pragma unroll
        for (int u = 0; u < TSEG; u++)
            vals[u] = g_Apre[base + (size_t)(g * TSEG + u) * S_];
    } else {
#pragma unroll
        for (int u = 0; u < TSEG; u++) vals[u] = 0.f;
    }

    // in-place exclusive prefix within group
    float run = 0.f;
#pragma unroll
    for (int u = 0; u < TSEG; u++) {
        float x = vals[u];
        vals[u] = run;
        run += x;
    }
    tot[g][sl] = run;
    __syncthreads();

    float off = 0.f;
#pragma unroll
    for (int gg = 0; gg < 3; gg++)
        if (gg < g) off += tot[gg][sl];

    if (act) {
#pragma unroll
        for (int u = 0; u < TSEG; u++)
            g_cov[base + (size_t)(g * TSEG + u) * S_] = off + vals[u];
    }
}

// ---------------------------------------------------------------------------
extern "C" void kernel_launch(void* const* d_in, const int* in_sizes, int n_in,
                              void* d_out, int out_size)
{
    const float*         dec    = (const float*)d_in[0];
    const float*         enc    = (const float*)d_in[1];
    const unsigned char* mask   = (const unsigned char*)d_in[2];
    const float*         W_h    = (const float*)d_in[3];
    const float*         W_s    = (const float*)d_in[4];
    const float*         w_c    = (const float*)d_in[5];
    const float*         v      = (const float*)d_in[6];
    const float*         b_attn = (const float*)d_in[7];

    float* out  = (float*)d_out;
    float* ctx  = out;
    float* Afin = out + (size_t)B_ * T_ * H_;
    float* loss = Afin + (size_t)B_ * T_ * S_;

    float* pWs = nullptr;
    cudaGetSymbolAddress((void**)&pWs, g_Ws);

    // WhT = (enc @ W_h + b_attn)^T — fused GEMM+transpose, 400 CTAs
    sgemmWhT<<<dim3(H_ / 32, (B_ * S_) / 64), 256>>>(enc, W_h, b_attn);
    // Ws = dec @ W_s
    sgemm64x32<<<dim3(H_ / 32, (B_ * T_ + 63) / 64), 256>>>(
        dec, W_s, pWs, B_ * T_, H_, H_);

    // Pass 1: A_prelim
    attn_pass<false><<<B_ * (T_ / TGT), NTH>>>(mask, v, nullptr, nullptr, nullptr);

    // Shifted cumsum over t (also zeroes loss slot)
    cumsum_k<<<dim3((S_ + 63) / 64, B_), 256>>>(loss);

    // Pass 2: A_final + cov_loss
    attn_pass<true><<<B_ * (T_ / TGT), NTH>>>(mask, v, w_c, Afin, loss);

    // context[b] = A_final[b] @ enc[b]
    sgemm32<<<dim3(H_ / 32, (T_ + 31) / 32, B_), 256>>>(
        Afin, enc, ctx, T_, H_, S_,
        (long long)T_ * S_, (long long)S_ * H_, (long long)T_ * H_);
}